// round 2
// baseline (speedup 1.0000x reference)
#include <cuda_runtime.h>
#include <cuda_bf16.h>

#define TOKENS 16384
#define DIM    768
#define QKVD   2304
#define NH     12
#define HD     64

// Scratch (device globals: allocation-free per harness rules)
__device__ float g_qkv[(size_t)TOKENS * QKVD];   // ~151 MB
__device__ float g_attn[(size_t)TOKENS * DIM];   // ~50 MB

// ---------------------------------------------------------------------------
// Tiled fp32 SGEMM: C[M,N] = A[M,K] @ W[N,K]^T
// MODE 0: A = external input (feature-masked per-row by k < d_e), C = g_qkv
// MODE 1: A = g_attn, C = external out, with bias add + output column mask
// BM=BN=128, BK=8, 256 threads, 8x8 micro-tile per thread.
// ---------------------------------------------------------------------------
template<int MODE>
__global__ __launch_bounds__(256)
void sgemm_kernel(const float* __restrict__ Aext,
                  float* __restrict__ Cext,
                  const float* __restrict__ W,
                  const int* __restrict__ emask,
                  const float* __restrict__ bias,
                  int M, int N, int K)
{
    __shared__ float As[8][128];
    __shared__ float Bs[8][128];
    __shared__ int   dlim[128];

    const float* A = (MODE == 0) ? Aext : g_attn;
    float*       C = (MODE == 0) ? g_qkv : Cext;

    const int tid = threadIdx.x;
    const int m0 = blockIdx.y * 128;
    const int n0 = blockIdx.x * 128;

    // per-row nested feature limit d_e = DIM >> (3 - expert)
    if (tid < 128) {
        int e = emask[m0 + tid];
        dlim[tid] = DIM >> (3 - e);
    }
    __syncthreads();

    const int lr = tid >> 1;          // load row 0..127
    const int lc = (tid & 1) * 4;     // load col 0 or 4

    const float* Aptr = A + (size_t)(m0 + lr) * K + lc;
    const float* Wptr = W + (size_t)(n0 + lr) * K + lc;

    const int tx = tid & 15;          // 0..15 -> 8 output cols each
    const int ty = tid >> 4;          // 0..15 -> 8 output rows each

    float acc[8][8];
    #pragma unroll
    for (int i = 0; i < 8; i++)
        #pragma unroll
        for (int j = 0; j < 8; j++)
            acc[i][j] = 0.f;

    const int alim = (MODE == 0) ? dlim[lr] : K;

    for (int k0 = 0; k0 < K; k0 += 8) {
        float4 a = *(const float4*)(Aptr + k0);
        if (MODE == 0) {
            int kb = k0 + lc;
            if (kb + 0 >= alim) a.x = 0.f;
            if (kb + 1 >= alim) a.y = 0.f;
            if (kb + 2 >= alim) a.z = 0.f;
            if (kb + 3 >= alim) a.w = 0.f;
        }
        float4 b = *(const float4*)(Wptr + k0);

        As[lc + 0][lr] = a.x; As[lc + 1][lr] = a.y;
        As[lc + 2][lr] = a.z; As[lc + 3][lr] = a.w;
        Bs[lc + 0][lr] = b.x; Bs[lc + 1][lr] = b.y;
        Bs[lc + 2][lr] = b.z; Bs[lc + 3][lr] = b.w;
        __syncthreads();

        #pragma unroll
        for (int kk = 0; kk < 8; kk++) {
            float ra[8], rb[8];
            #pragma unroll
            for (int i = 0; i < 8; i++) ra[i] = As[kk][ty * 8 + i];
            #pragma unroll
            for (int j = 0; j < 8; j++) rb[j] = Bs[kk][tx * 8 + j];
            #pragma unroll
            for (int i = 0; i < 8; i++)
                #pragma unroll
                for (int j = 0; j < 8; j++)
                    acc[i][j] += ra[i] * rb[j];
        }
        __syncthreads();
    }

    // store 8x8 tile with float4 stores
    #pragma unroll
    for (int i = 0; i < 8; i++) {
        const int mrow = ty * 8 + i;
        float* Crow = C + (size_t)(m0 + mrow) * N + n0 + tx * 8;
        if (MODE == 0) {
            *(float4*)(Crow + 0) = make_float4(acc[i][0], acc[i][1], acc[i][2], acc[i][3]);
            *(float4*)(Crow + 4) = make_float4(acc[i][4], acc[i][5], acc[i][6], acc[i][7]);
        } else {
            const int lim = dlim[mrow];
            float v[8];
            #pragma unroll
            for (int j = 0; j < 8; j++) {
                int n = n0 + tx * 8 + j;
                float t = acc[i][j] + bias[n];
                v[j] = (n < lim) ? t : 0.f;
            }
            *(float4*)(Crow + 0) = make_float4(v[0], v[1], v[2], v[3]);
            *(float4*)(Crow + 4) = make_float4(v[4], v[5], v[6], v[7]);
        }
    }
}

// ---------------------------------------------------------------------------
// Per-token attention over heads axis: scores[12][12] from q,k [12,64],
// softmax over s, out = attn @ v. One block (12 warps) per token; warp = head.
// ---------------------------------------------------------------------------
__global__ __launch_bounds__(384)
void attn_kernel()
{
    __shared__ float ks[NH * HD];
    __shared__ float vs[NH * HD];

    const int tok = blockIdx.x;
    const float* base = g_qkv + (size_t)tok * QKVD;
    const int tid = threadIdx.x;

    for (int i = tid; i < NH * HD; i += 384) {
        ks[i] = base[DIM + i];        // k
        vs[i] = base[2 * DIM + i];    // v
    }

    const int h = tid >> 5;     // head (warp id)
    const int lane = tid & 31;

    const float qa = base[h * HD + lane];
    const float qb = base[h * HD + 32 + lane];
    __syncthreads();

    float sc[NH];
    #pragma unroll
    for (int s = 0; s < NH; s++) {
        float p = qa * ks[s * HD + lane] + qb * ks[s * HD + 32 + lane];
        p += __shfl_xor_sync(0xffffffffu, p, 16);
        p += __shfl_xor_sync(0xffffffffu, p, 8);
        p += __shfl_xor_sync(0xffffffffu, p, 4);
        p += __shfl_xor_sync(0xffffffffu, p, 2);
        p += __shfl_xor_sync(0xffffffffu, p, 1);
        sc[s] = p * 0.125f;   // HEAD_DIM^-0.5 = 64^-0.5
    }

    float mx = sc[0];
    #pragma unroll
    for (int s = 1; s < NH; s++) mx = fmaxf(mx, sc[s]);
    float sum = 0.f;
    #pragma unroll
    for (int s = 0; s < NH; s++) { sc[s] = expf(sc[s] - mx); sum += sc[s]; }
    const float inv = 1.f / sum;

    float oa = 0.f, ob = 0.f;
    #pragma unroll
    for (int s = 0; s < NH; s++) {
        float w = sc[s] * inv;
        oa += w * vs[s * HD + lane];
        ob += w * vs[s * HD + 32 + lane];
    }

    float* orow = g_attn + (size_t)tok * DIM + h * HD;
    orow[lane] = oa;
    orow[32 + lane] = ob;
}

// ---------------------------------------------------------------------------
extern "C" void kernel_launch(void* const* d_in, const int* in_sizes, int n_in,
                              void* d_out, int out_size)
{
    const float* x      = (const float*)d_in[0];
    const int*   emask  = (const int*)d_in[1];
    const float* qkv_w  = (const float*)d_in[2];
    const float* proj_w = (const float*)d_in[3];
    const float* proj_b = (const float*)d_in[4];
    float* out = (float*)d_out;

    // GEMM1: [16384,768] x [768,2304]^T -> g_qkv, A masked per-row
    dim3 g1(QKVD / 128, TOKENS / 128);
    sgemm_kernel<0><<<g1, 256>>>(x, nullptr, qkv_w, emask, nullptr,
                                 TOKENS, QKVD, DIM);

    // Attention: one block per token
    attn_kernel<<<TOKENS, 384>>>();

    // GEMM2: [16384,768] x [768,768]^T + bias, output masked -> out
    dim3 g2(DIM / 128, TOKENS / 128);
    sgemm_kernel<1><<<g2, 256>>>(nullptr, out, proj_w, emask, proj_b,
                                 TOKENS, DIM, DIM);
}

// round 4
// speedup vs baseline: 2.0026x; 2.0026x over previous
#include <cuda_runtime.h>
#include <cuda_bf16.h>

#define TOKENS 16384
#define DIM    768
#define QKVD   2304
#define NH     12
#define HD     64
#define BMAX   132

// Scratch (device globals: allocation-free per harness rules)
__device__ float g_qkv[(size_t)TOKENS * QKVD];   // ~151 MB
__device__ float g_attn[(size_t)TOKENS * DIM];   // ~50 MB

// expert bucketing state
__device__ int g_cnt[4];
__device__ int g_off[4];
__device__ int g_perm[TOKENS];
__device__ int g_bmap_d[BMAX];   // bucket feature width d_e
__device__ int g_bmap_s[BMAX];   // start row in permuted order
__device__ int g_bmap_e[BMAX];   // end row (exclusive); e<=s => invalid block

// ---------------------------------------------------------------------------
__global__ void zero_cnt_kernel() {
    if (threadIdx.x < 4) g_cnt[threadIdx.x] = 0;
}

__global__ void count_kernel(const int* __restrict__ emask) {
    int t = blockIdx.x * blockDim.x + threadIdx.x;
    if (t < TOKENS) atomicAdd(&g_cnt[emask[t]], 1);
}

__global__ void build_kernel() {
    // single thread: offsets + block map, then reset counters for scatter
    int off = 0, idx = 0;
    for (int e = 0; e < 4; e++) {
        int c = g_cnt[e];
        int d = DIM >> (3 - e);
        g_off[e] = off;
        for (int b = off; b < off + c; b += 128) {
            g_bmap_d[idx] = d;
            g_bmap_s[idx] = b;
            int en = b + 128; if (en > off + c) en = off + c;
            g_bmap_e[idx] = en;
            idx++;
        }
        off += c;
    }
    for (; idx < BMAX; idx++) { g_bmap_s[idx] = 0; g_bmap_e[idx] = 0; g_bmap_d[idx] = 96; }
    for (int e = 0; e < 4; e++) g_cnt[e] = 0;
}

__global__ void scatter_kernel(const int* __restrict__ emask) {
    int t = blockIdx.x * blockDim.x + threadIdx.x;
    if (t < TOKENS) {
        int e = emask[t];
        int pos = g_off[e] + atomicAdd(&g_cnt[e], 1);
        g_perm[pos] = t;
    }
}

// ---------------------------------------------------------------------------
// Expert-sorted tiled SGEMM: C[row] = A[row,:K_eff] @ W^T (+bias, col mask)
// MODE 0: A = x (external), C = g_qkv, K-loop bound = bucket d (uniform!)
// MODE 1: A = g_attn, C = out, K = 768, cols >= d zeroed, + bias.
// BM=BN=128, BK=8, 256 threads, 8x8 microtile, float4 LDS, reg prefetch.
// ---------------------------------------------------------------------------
template<int MODE>
__global__ __launch_bounds__(256)
void sgemm_sorted(const float* __restrict__ Aext,
                  float* __restrict__ Cext,
                  const float* __restrict__ W,
                  const float* __restrict__ bias,
                  int N, int K)
{
    __shared__ float As[8][128];
    __shared__ float Bs[8][128];
    __shared__ int   srow[128];

    const int bm = blockIdx.y;
    const int s  = g_bmap_s[bm];
    const int e  = g_bmap_e[bm];
    if (e <= s) return;
    const int d  = g_bmap_d[bm];
    const int n0 = blockIdx.x * 128;

    const float* A = (MODE == 0) ? Aext : g_attn;
    float*       C = (MODE == 0) ? g_qkv : Cext;

    const int tid = threadIdx.x;
    if (tid < 128) {
        int g = s + tid;
        srow[tid] = (g < e) ? g_perm[g] : -1;
    }
    __syncthreads();

    const int tx = tid & 15;
    const int ty = tid >> 4;

    // MODE 1: tiles entirely beyond the bucket's feature width -> zero-fill
    if (MODE == 1 && n0 >= d) {
        const float4 z = make_float4(0.f, 0.f, 0.f, 0.f);
        #pragma unroll
        for (int i = 0; i < 8; i++) {
            int tok = srow[ty * 8 + i];
            if (tok >= 0) {
                float* Crow = C + (size_t)tok * N + n0 + tx * 8;
                *(float4*)(Crow + 0) = z;
                *(float4*)(Crow + 4) = z;
            }
        }
        return;
    }

    const int lr = tid >> 1;
    const int lc = (tid & 1) * 4;

    int atok = srow[lr]; if (atok < 0) atok = srow[0];
    const float* Aptr = A + (size_t)atok * K + lc;
    const float* Wptr = W + (size_t)(n0 + lr) * K + lc;

    const int Klim = (MODE == 0) ? d : K;

    float acc[8][8];
    #pragma unroll
    for (int i = 0; i < 8; i++)
        #pragma unroll
        for (int j = 0; j < 8; j++) acc[i][j] = 0.f;

    float4 a = *(const float4*)(Aptr);
    float4 b = *(const float4*)(Wptr);

    for (int k0 = 0; k0 < Klim; k0 += 8) {
        As[lc + 0][lr] = a.x; As[lc + 1][lr] = a.y;
        As[lc + 2][lr] = a.z; As[lc + 3][lr] = a.w;
        Bs[lc + 0][lr] = b.x; Bs[lc + 1][lr] = b.y;
        Bs[lc + 2][lr] = b.z; Bs[lc + 3][lr] = b.w;
        __syncthreads();

        if (k0 + 8 < Klim) {
            a = *(const float4*)(Aptr + k0 + 8);
            b = *(const float4*)(Wptr + k0 + 8);
        }

        #pragma unroll
        for (int kk = 0; kk < 8; kk++) {
            float4 ra0 = *(const float4*)&As[kk][ty * 8];
            float4 ra1 = *(const float4*)&As[kk][ty * 8 + 4];
            float4 rb0 = *(const float4*)&Bs[kk][tx * 8];
            float4 rb1 = *(const float4*)&Bs[kk][tx * 8 + 4];
            float ra[8] = {ra0.x, ra0.y, ra0.z, ra0.w, ra1.x, ra1.y, ra1.z, ra1.w};
            float rb[8] = {rb0.x, rb0.y, rb0.z, rb0.w, rb1.x, rb1.y, rb1.z, rb1.w};
            #pragma unroll
            for (int i = 0; i < 8; i++)
                #pragma unroll
                for (int j = 0; j < 8; j++)
                    acc[i][j] += ra[i] * rb[j];
        }
        __syncthreads();
    }

    #pragma unroll
    for (int i = 0; i < 8; i++) {
        const int tok = srow[ty * 8 + i];
        if (tok < 0) continue;
        float* Crow = C + (size_t)tok * N + n0 + tx * 8;
        if (MODE == 0) {
            *(float4*)(Crow + 0) = make_float4(acc[i][0], acc[i][1], acc[i][2], acc[i][3]);
            *(float4*)(Crow + 4) = make_float4(acc[i][4], acc[i][5], acc[i][6], acc[i][7]);
        } else {
            float v[8];
            #pragma unroll
            for (int j = 0; j < 8; j++) {
                int n = n0 + tx * 8 + j;
                float t = acc[i][j] + bias[n];
                v[j] = (n < d) ? t : 0.f;
            }
            *(float4*)(Crow + 0) = make_float4(v[0], v[1], v[2], v[3]);
            *(float4*)(Crow + 4) = make_float4(v[4], v[5], v[6], v[7]);
        }
    }
}

// ---------------------------------------------------------------------------
// Per-token attention over heads axis (12x12 softmax). Warp = head.
// ---------------------------------------------------------------------------
__global__ __launch_bounds__(384)
void attn_kernel()
{
    __shared__ float ks[NH * HD];
    __shared__ float vs[NH * HD];

    const int tok = blockIdx.x;
    const float* base = g_qkv + (size_t)tok * QKVD;
    const int tid = threadIdx.x;

    for (int i = tid; i < NH * HD; i += 384) {
        ks[i] = base[DIM + i];
        vs[i] = base[2 * DIM + i];
    }

    const int h = tid >> 5;
    const int lane = tid & 31;

    const float qa = base[h * HD + lane];
    const float qb = base[h * HD + 32 + lane];
    __syncthreads();

    float sc[NH];
    #pragma unroll
    for (int s = 0; s < NH; s++) {
        float p = qa * ks[s * HD + lane] + qb * ks[s * HD + 32 + lane];
        p += __shfl_xor_sync(0xffffffffu, p, 16);
        p += __shfl_xor_sync(0xffffffffu, p, 8);
        p += __shfl_xor_sync(0xffffffffu, p, 4);
        p += __shfl_xor_sync(0xffffffffu, p, 2);
        p += __shfl_xor_sync(0xffffffffu, p, 1);
        sc[s] = p * 0.125f;
    }

    float mx = sc[0];
    #pragma unroll
    for (int s = 1; s < NH; s++) mx = fmaxf(mx, sc[s]);
    float sum = 0.f;
    #pragma unroll
    for (int s = 0; s < NH; s++) { sc[s] = expf(sc[s] - mx); sum += sc[s]; }
    const float inv = 1.f / sum;

    float oa = 0.f, ob = 0.f;
    #pragma unroll
    for (int s = 0; s < NH; s++) {
        float w = sc[s] * inv;
        oa += w * vs[s * HD + lane];
        ob += w * vs[s * HD + 32 + lane];
    }

    float* orow = g_attn + (size_t)tok * DIM + h * HD;
    orow[lane] = oa;
    orow[32 + lane] = ob;
}

// ---------------------------------------------------------------------------
extern "C" void kernel_launch(void* const* d_in, const int* in_sizes, int n_in,
                              void* d_out, int out_size)
{
    const float* x      = (const float*)d_in[0];
    const int*   emask  = (const int*)d_in[1];
    const float* qkv_w  = (const float*)d_in[2];
    const float* proj_w = (const float*)d_in[3];
    const float* proj_b = (const float*)d_in[4];
    float* out = (float*)d_out;

    // expert bucketing (tiny kernels)
    zero_cnt_kernel<<<1, 32>>>();
    count_kernel<<<TOKENS / 256, 256>>>(emask);
    build_kernel<<<1, 1>>>();
    scatter_kernel<<<TOKENS / 256, 256>>>(emask);

    // GEMM1: per-bucket uniform K = d_e
    dim3 g1(QKVD / 128, BMAX);
    sgemm_sorted<0><<<g1, 256>>>(x, nullptr, qkv_w, nullptr, QKVD, DIM);

    // Attention: one block per token
    attn_kernel<<<TOKENS, 384>>>();

    // GEMM2: full K, output column tiles beyond d_e are zero-filled
    dim3 g2(DIM / 128, BMAX);
    sgemm_sorted<1><<<g2, 256>>>(nullptr, out, proj_w, proj_b, DIM, DIM);
}

// round 6
// speedup vs baseline: 3.7670x; 1.8811x over previous
#include <cuda_runtime.h>
#include <cuda_bf16.h>
#include <cstdint>

#define TOKENS 16384
#define DIM    768
#define QKVD   2304
#define NH     12
#define HD     64
#define BMAX   132

// ---------------- device global scratch (allocation-free) -------------------
__device__ float g_qkv[(size_t)TOKENS * QKVD];            // fp32 qkv (attn reads)
__device__ __nv_bfloat16 g_xh[(size_t)TOKENS * DIM];      // x split hi/lo
__device__ __nv_bfloat16 g_xl[(size_t)TOKENS * DIM];
__device__ __nv_bfloat16 g_ah[(size_t)TOKENS * DIM];      // attn out split
__device__ __nv_bfloat16 g_al[(size_t)TOKENS * DIM];
__device__ __nv_bfloat16 g_wqh[(size_t)QKVD * DIM];       // qkv_w split
__device__ __nv_bfloat16 g_wql[(size_t)QKVD * DIM];
__device__ __nv_bfloat16 g_wph[(size_t)DIM * DIM];        // proj_w split
__device__ __nv_bfloat16 g_wpl[(size_t)DIM * DIM];

// bucketing state
__device__ int g_cnt[4];
__device__ int g_off[4];
__device__ int g_perm[TOKENS];
__device__ int g_bmap_d[BMAX];
__device__ int g_bmap_s[BMAX];
__device__ int g_bmap_e[BMAX];

// ---------------- PTX helpers ----------------------------------------------
__device__ __forceinline__ uint32_t smem_u32(const void* p) {
    uint32_t a;
    asm("{ .reg .u64 t; cvta.to.shared.u64 t, %1; cvt.u32.u64 %0, t; }" : "=r"(a) : "l"(p));
    return a;
}

#define CP_ASYNC16(dst, src) \
    asm volatile("cp.async.cg.shared.global [%0], [%1], 16;" :: "r"(dst), "l"(src) : "memory")
#define CP_COMMIT() asm volatile("cp.async.commit_group;" ::: "memory")
#define CP_WAIT(n)  asm volatile("cp.async.wait_group %0;" :: "n"(n) : "memory")

#define LDMATRIX_X4(r0, r1, r2, r3, addr) \
    asm volatile("ldmatrix.sync.aligned.m8n8.x4.shared.b16 {%0,%1,%2,%3}, [%4];" \
                 : "=r"(r0), "=r"(r1), "=r"(r2), "=r"(r3) : "r"(addr))

#define MMA_BF16(c, a0, a1, a2, a3, b0, b1) \
    asm volatile("mma.sync.aligned.m16n8k16.row.col.f32.bf16.bf16.f32 " \
                 "{%0,%1,%2,%3}, {%4,%5,%6,%7}, {%8,%9}, {%0,%1,%2,%3};" \
                 : "+f"((c)[0]), "+f"((c)[1]), "+f"((c)[2]), "+f"((c)[3]) \
                 : "r"(a0), "r"(a1), "r"(a2), "r"(a3), "r"(b0), "r"(b1))

// ---------------- setup kernels ---------------------------------------------
__global__ void zero_cnt_kernel() { if (threadIdx.x < 4) g_cnt[threadIdx.x] = 0; }

__global__ void count_kernel(const int* __restrict__ emask) {
    int t = blockIdx.x * blockDim.x + threadIdx.x;
    if (t < TOKENS) atomicAdd(&g_cnt[emask[t]], 1);
}

__global__ void build_kernel() {
    int off = 0, idx = 0;
    for (int e = 0; e < 4; e++) {
        int c = g_cnt[e];
        int d = DIM >> (3 - e);
        g_off[e] = off;
        for (int b = off; b < off + c; b += 128) {
            g_bmap_d[idx] = d;
            g_bmap_s[idx] = b;
            int en = b + 128; if (en > off + c) en = off + c;
            g_bmap_e[idx] = en;
            idx++;
        }
        off += c;
    }
    for (; idx < BMAX; idx++) { g_bmap_s[idx] = 0; g_bmap_e[idx] = 0; g_bmap_d[idx] = 96; }
    for (int e = 0; e < 4; e++) g_cnt[e] = 0;
}

__global__ void scatter_kernel(const int* __restrict__ emask) {
    int t = blockIdx.x * blockDim.x + threadIdx.x;
    if (t < TOKENS) {
        int e = emask[t];
        int pos = g_off[e] + atomicAdd(&g_cnt[e], 1);
        g_perm[pos] = t;
    }
}

// split fp32 -> bf16 hi + bf16 lo.  T: 0 = x, 1 = qkv_w, 2 = proj_w
template<int T>
__global__ void convert_kernel(const float* __restrict__ src, int n4) {
    int i = blockIdx.x * blockDim.x + threadIdx.x;
    if (i >= n4) return;
    __nv_bfloat16* Gh = (T == 0) ? g_xh : (T == 1) ? g_wqh : g_wph;
    __nv_bfloat16* Gl = (T == 0) ? g_xl : (T == 1) ? g_wql : g_wpl;
    float4 v = ((const float4*)src)[i];
    __nv_bfloat16 h0 = __float2bfloat16(v.x), h1 = __float2bfloat16(v.y);
    __nv_bfloat16 h2 = __float2bfloat16(v.z), h3 = __float2bfloat16(v.w);
    __nv_bfloat16 l0 = __float2bfloat16(v.x - __bfloat162float(h0));
    __nv_bfloat16 l1 = __float2bfloat16(v.y - __bfloat162float(h1));
    __nv_bfloat16 l2 = __float2bfloat16(v.z - __bfloat162float(h2));
    __nv_bfloat16 l3 = __float2bfloat16(v.w - __bfloat162float(h3));
    ((ushort4*)Gh)[i] = make_ushort4(__bfloat16_as_ushort(h0), __bfloat16_as_ushort(h1),
                                     __bfloat16_as_ushort(h2), __bfloat16_as_ushort(h3));
    ((ushort4*)Gl)[i] = make_ushort4(__bfloat16_as_ushort(l0), __bfloat16_as_ushort(l1),
                                     __bfloat16_as_ushort(l2), __bfloat16_as_ushort(l3));
}

// ---------------- tensor-core GEMM (mma.sync split-bf16) --------------------
// MODE 0: g_qkv[token][2304] = x_split @ qkv_w^T, K = bucket d (mult of 32)
// MODE 1: out[token][768]    = attn_split @ proj_w^T + bias, cols>=d zeroed
// Block 128x128, 8 warps (2M x 4N), warp tile 64x32, BK=32, double-buffered.
// SMEM layout: [0,512) srow; [1024, +2*32768) stages.
// Stage: A_hi 8K | A_lo 8K | B_hi 8K | B_lo 8K. Rows of 32 bf16 (64B = 4 x 16B
// chunks), chunk swizzle: ch ^ (row & 3).
#define STG_OFF   1024
#define STG_BYTES 32768
#define SMEM_TOTAL (STG_OFF + 2 * STG_BYTES)

template<int MODE>
__global__ __launch_bounds__(256)
void gemm_mma(float* __restrict__ Cext, const float* __restrict__ bias)
{
    extern __shared__ char smem[];
    const uint32_t sbase = smem_u32(smem);

    const int bm = blockIdx.y;
    const int s  = g_bmap_s[bm];
    const int e  = g_bmap_e[bm];
    if (e <= s) return;
    const int d  = g_bmap_d[bm];
    const int n0 = blockIdx.x * 128;

    const int N = (MODE == 0) ? QKVD : DIM;
    float* C = (MODE == 0) ? g_qkv : Cext;
    const __nv_bfloat16* Ah = (MODE == 0) ? g_xh : g_ah;
    const __nv_bfloat16* Al = (MODE == 0) ? g_xl : g_al;
    const __nv_bfloat16* Bh = (MODE == 0) ? g_wqh : g_wph;
    const __nv_bfloat16* Bl = (MODE == 0) ? g_wql : g_wpl;

    const int tid  = threadIdx.x;
    const int wid  = tid >> 5;
    const int lane = tid & 31;

    int* srow = (int*)smem;
    if (tid < 128) {
        int g = s + tid;
        srow[tid] = (g < e) ? g_perm[g] : -1;
    }
    __syncthreads();

    if (MODE == 1 && n0 >= d) {
        const float4 z = make_float4(0.f, 0.f, 0.f, 0.f);
        for (int i = 0; i < 16; i++) {
            int tok = srow[wid * 16 + i];
            if (tok >= 0)
                *(float4*)(C + (size_t)tok * N + n0 + lane * 4) = z;
        }
        return;
    }

    const int tok0 = srow[0];
    const int Klim = (MODE == 0) ? d : DIM;
    const int nc = Klim / 32;

    // fill assignment: idx -> (row, 16B chunk)
    const int frow0 = tid >> 2;             // part 0 rows 0..63
    const int fch   = tid & 3;
    const uint32_t fso = (uint32_t)((fch ^ (frow0 & 3)) * 16 + frow0 * 64);
    const int frow1 = frow0 + 64;           // part 1 rows 64..127
    const uint32_t fso1 = (uint32_t)((fch ^ (frow1 & 3)) * 16 + frow1 * 64);

    int ftok0 = srow[frow0]; if (ftok0 < 0) ftok0 = tok0;
    int ftok1 = srow[frow1]; if (ftok1 < 0) ftok1 = tok0;
    const __nv_bfloat16* aH0 = Ah + (size_t)ftok0 * DIM + fch * 8;
    const __nv_bfloat16* aL0 = Al + (size_t)ftok0 * DIM + fch * 8;
    const __nv_bfloat16* aH1 = Ah + (size_t)ftok1 * DIM + fch * 8;
    const __nv_bfloat16* aL1 = Al + (size_t)ftok1 * DIM + fch * 8;
    const __nv_bfloat16* bH0 = Bh + (size_t)(n0 + frow0) * DIM + fch * 8;
    const __nv_bfloat16* bL0 = Bl + (size_t)(n0 + frow0) * DIM + fch * 8;
    const __nv_bfloat16* bH1 = Bh + (size_t)(n0 + frow1) * DIM + fch * 8;
    const __nv_bfloat16* bL1 = Bl + (size_t)(n0 + frow1) * DIM + fch * 8;

    // warp tiling
    const int wm = wid & 1;       // 0..1 -> 64 rows
    const int wn = wid >> 1;      // 0..3 -> 32 cols

    // ldmatrix row/lane precompute
    int a_row[4];
    #pragma unroll
    for (int mi = 0; mi < 4; mi++) a_row[mi] = wm * 64 + mi * 16 + (lane & 15);
    const int a_cb = lane >> 4;                       // +0/+1 chunk
    int b_row[2];
    #pragma unroll
    for (int j = 0; j < 2; j++)
        b_row[j] = wn * 32 + j * 16 + ((lane >> 4) << 3) + (lane & 7);
    const int b_cb = (lane >> 3) & 1;

    float acc[4][4][4];
    #pragma unroll
    for (int mi = 0; mi < 4; mi++)
        #pragma unroll
        for (int nj = 0; nj < 4; nj++)
            #pragma unroll
            for (int q = 0; q < 4; q++) acc[mi][nj][q] = 0.f;

    // prologue: load chunk 0 into stage 0
    {
        const uint32_t stg = sbase + STG_OFF;
        CP_ASYNC16(stg + 0     + fso,  aH0);
        CP_ASYNC16(stg + 8192  + fso,  aL0);
        CP_ASYNC16(stg + 16384 + fso,  bH0);
        CP_ASYNC16(stg + 24576 + fso,  bL0);
        CP_ASYNC16(stg + 0     + fso1, aH1);
        CP_ASYNC16(stg + 8192  + fso1, aL1);
        CP_ASYNC16(stg + 16384 + fso1, bH1);
        CP_ASYNC16(stg + 24576 + fso1, bL1);
        CP_COMMIT();
    }

    for (int i = 0; i < nc; i++) {
        if (i + 1 < nc) {
            const int k0 = (i + 1) * 32;
            const uint32_t stg = sbase + STG_OFF + ((i + 1) & 1) * STG_BYTES;
            CP_ASYNC16(stg + 0     + fso,  aH0 + k0);
            CP_ASYNC16(stg + 8192  + fso,  aL0 + k0);
            CP_ASYNC16(stg + 16384 + fso,  bH0 + k0);
            CP_ASYNC16(stg + 24576 + fso,  bL0 + k0);
            CP_ASYNC16(stg + 0     + fso1, aH1 + k0);
            CP_ASYNC16(stg + 8192  + fso1, aL1 + k0);
            CP_ASYNC16(stg + 16384 + fso1, bH1 + k0);
            CP_ASYNC16(stg + 24576 + fso1, bL1 + k0);
            CP_COMMIT();
            CP_WAIT(1);
        } else {
            CP_WAIT(0);
        }
        __syncthreads();

        const uint32_t stg = sbase + STG_OFF + (i & 1) * STG_BYTES;
        #pragma unroll
        for (int kk = 0; kk < 32; kk += 16) {
            const int acb = kk / 8 + a_cb;
            const int bcb = kk / 8 + b_cb;
            uint32_t ah[4][4], al[4][4], bhf[2][4], blf[2][4];
            #pragma unroll
            for (int mi = 0; mi < 4; mi++) {
                const uint32_t ao = (uint32_t)(a_row[mi] * 64 + ((acb ^ (a_row[mi] & 3)) * 16));
                LDMATRIX_X4(ah[mi][0], ah[mi][1], ah[mi][2], ah[mi][3], stg + 0 + ao);
                LDMATRIX_X4(al[mi][0], al[mi][1], al[mi][2], al[mi][3], stg + 8192 + ao);
            }
            #pragma unroll
            for (int j = 0; j < 2; j++) {
                const uint32_t bo = (uint32_t)(b_row[j] * 64 + ((bcb ^ (b_row[j] & 3)) * 16));
                LDMATRIX_X4(bhf[j][0], bhf[j][1], bhf[j][2], bhf[j][3], stg + 16384 + bo);
                LDMATRIX_X4(blf[j][0], blf[j][1], blf[j][2], blf[j][3], stg + 24576 + bo);
            }
            #pragma unroll
            for (int mi = 0; mi < 4; mi++) {
                #pragma unroll
                for (int nj = 0; nj < 4; nj++) {
                    const int j = nj >> 1, p = (nj & 1) * 2;
                    MMA_BF16(acc[mi][nj], ah[mi][0], ah[mi][1], ah[mi][2], ah[mi][3],
                             bhf[j][p], bhf[j][p + 1]);
                    MMA_BF16(acc[mi][nj], ah[mi][0], ah[mi][1], ah[mi][2], ah[mi][3],
                             blf[j][p], blf[j][p + 1]);
                    MMA_BF16(acc[mi][nj], al[mi][0], al[mi][1], al[mi][2], al[mi][3],
                             bhf[j][p], bhf[j][p + 1]);
                }
            }
        }
        __syncthreads();
    }

    // epilogue: 2 halves of 64 rows via smem transpose, coalesced gathered rows
    float* T = (float*)(smem + STG_OFF);
    float4 bb = make_float4(0.f, 0.f, 0.f, 0.f);
    if (MODE == 1) bb = *(const float4*)(bias + n0 + lane * 4);

    #pragma unroll
    for (int half = 0; half < 2; half++) {
        if (wm == half) {
            #pragma unroll
            for (int mi = 0; mi < 4; mi++) {
                #pragma unroll
                for (int nj = 0; nj < 4; nj++) {
                    const int r  = mi * 16 + (lane >> 2);
                    const int cc = wn * 32 + nj * 8 + 2 * (lane & 3);
                    *(float2*)&T[r * 132 + cc]       = make_float2(acc[mi][nj][0], acc[mi][nj][1]);
                    *(float2*)&T[(r + 8) * 132 + cc] = make_float2(acc[mi][nj][2], acc[mi][nj][3]);
                }
            }
        }
        __syncthreads();

        #pragma unroll
        for (int q = 0; q < 8; q++) {
            const int rr = wid * 8 + q;
            const int tok = srow[half * 64 + rr];
            if (tok < 0) continue;
            float4 v = *(float4*)&T[rr * 132 + lane * 4];
            if (MODE == 1) {
                const int n = n0 + lane * 4;
                v.x = (n + 0 < d) ? v.x + bb.x : 0.f;
                v.y = (n + 1 < d) ? v.y + bb.y : 0.f;
                v.z = (n + 2 < d) ? v.z + bb.z : 0.f;
                v.w = (n + 3 < d) ? v.w + bb.w : 0.f;
            }
            *(float4*)(C + (size_t)tok * N + n0 + lane * 4) = v;
        }
        __syncthreads();
    }
}

// ---------------- attention (12x12 over heads), outputs bf16 split ----------
__global__ __launch_bounds__(384)
void attn_kernel()
{
    __shared__ float ks[NH * HD];
    __shared__ float vs[NH * HD];

    const int tok = blockIdx.x;
    const float* base = g_qkv + (size_t)tok * QKVD;
    const int tid = threadIdx.x;

    for (int i = tid; i < NH * HD; i += 384) {
        ks[i] = base[DIM + i];
        vs[i] = base[2 * DIM + i];
    }

    const int h = tid >> 5;
    const int lane = tid & 31;

    const float qa = base[h * HD + lane];
    const float qb = base[h * HD + 32 + lane];
    __syncthreads();

    float sc[NH];
    #pragma unroll
    for (int s = 0; s < NH; s++) {
        float p = qa * ks[s * HD + lane] + qb * ks[s * HD + 32 + lane];
        p += __shfl_xor_sync(0xffffffffu, p, 16);
        p += __shfl_xor_sync(0xffffffffu, p, 8);
        p += __shfl_xor_sync(0xffffffffu, p, 4);
        p += __shfl_xor_sync(0xffffffffu, p, 2);
        p += __shfl_xor_sync(0xffffffffu, p, 1);
        sc[s] = p * 0.125f;
    }

    float mx = sc[0];
    #pragma unroll
    for (int s = 1; s < NH; s++) mx = fmaxf(mx, sc[s]);
    float sum = 0.f;
    #pragma unroll
    for (int s = 0; s < NH; s++) { sc[s] = expf(sc[s] - mx); sum += sc[s]; }
    const float inv = 1.f / sum;

    float oa = 0.f, ob = 0.f;
    #pragma unroll
    for (int s = 0; s < NH; s++) {
        float w = sc[s] * inv;
        oa += w * vs[s * HD + lane];
        ob += w * vs[s * HD + 32 + lane];
    }

    const size_t o = (size_t)tok * DIM + h * HD;
    __nv_bfloat16 ha = __float2bfloat16(oa);
    __nv_bfloat16 hb = __float2bfloat16(ob);
    g_ah[o + lane]      = ha;
    g_ah[o + 32 + lane] = hb;
    g_al[o + lane]      = __float2bfloat16(oa - __bfloat162float(ha));
    g_al[o + 32 + lane] = __float2bfloat16(ob - __bfloat162float(hb));
}

// ---------------------------------------------------------------------------
extern "C" void kernel_launch(void* const* d_in, const int* in_sizes, int n_in,
                              void* d_out, int out_size)
{
    const float* x      = (const float*)d_in[0];
    const int*   emask  = (const int*)d_in[1];
    const float* qkv_w  = (const float*)d_in[2];
    const float* proj_w = (const float*)d_in[3];
    const float* proj_b = (const float*)d_in[4];
    float* out = (float*)d_out;

    cudaFuncSetAttribute(gemm_mma<0>, cudaFuncAttributeMaxDynamicSharedMemorySize, SMEM_TOTAL);
    cudaFuncSetAttribute(gemm_mma<1>, cudaFuncAttributeMaxDynamicSharedMemorySize, SMEM_TOTAL);

    zero_cnt_kernel<<<1, 32>>>();
    count_kernel<<<TOKENS / 256, 256>>>(emask);
    build_kernel<<<1, 1>>>();
    scatter_kernel<<<TOKENS / 256, 256>>>(emask);

    convert_kernel<0><<<(TOKENS * DIM / 4 + 255) / 256, 256>>>(x, TOKENS * DIM / 4);
    convert_kernel<1><<<(QKVD * DIM / 4 + 255) / 256, 256>>>(qkv_w, QKVD * DIM / 4);
    convert_kernel<2><<<(DIM * DIM / 4 + 255) / 256, 256>>>(proj_w, DIM * DIM / 4);

    dim3 g1(QKVD / 128, BMAX);
    gemm_mma<0><<<g1, 256, SMEM_TOTAL>>>(nullptr, nullptr);

    attn_kernel<<<TOKENS, 384>>>();

    dim3 g2(DIM / 128, BMAX);
    gemm_mma<1><<<g2, 256, SMEM_TOTAL>>>(out, proj_b);
}